// round 1
// baseline (speedup 1.0000x reference)
#include <cuda_runtime.h>
#include <cuda_bf16.h>
#include <math.h>

// ---------------------------------------------------------------------------
// Problem constants
// ---------------------------------------------------------------------------
#define BATCH   4
#define DIM     192
#define HEADS   8
#define HEADDIM 24          // 192 / 8
#define HIDDEN  510         // int(192 * 2.66)
#define HGT     128
#define WID     128
#define HW      16384       // 128*128
#define NSPLIT  32          // split-K partials for q@k^T

// scratch pool layout (floats)
#define N_XN      ((size_t)BATCH * DIM * HW)          // 12,582,912
#define N_QKV     (3 * N_XN)                          // 37,748,736
#define N_H       ((size_t)BATCH * 2 * HIDDEN * HW)   // 66,846,720
#define N_G       ((size_t)BATCH * HIDDEN * HW)       // 33,423,360

#define OF_XN       ((size_t)0)
#define OF_QKV      (OF_XN + N_XN)
#define OF_QKV2     (OF_QKV + N_QKV)
#define OF_ATTNOUT  (OF_QKV2 + N_QKV)
#define OF_Y        (OF_ATTNOUT + N_XN)
#define OF_H1       (OF_Y + N_XN)
#define OF_H2       (OF_H1 + N_H)
#define OF_G        (OF_H2 + N_H)
#define OF_PATTN    (OF_G + N_G)
#define OF_ATTN     (OF_PATTN + (size_t)BATCH * HEADS * NSPLIT * HEADDIM * HEADDIM)
#define POOL_TOTAL  (OF_ATTN + (size_t)BATCH * HEADS * HEADDIM * HEADDIM)

__device__ __align__(128) float g_pool[POOL_TOTAL];

// ---------------------------------------------------------------------------
// Channel LayerNorm over NCHW channel dim (192), per pixel
// ---------------------------------------------------------------------------
__global__ void ln_chan_kernel(const float* __restrict__ x,
                               const float* __restrict__ w,
                               const float* __restrict__ bia,
                               float* __restrict__ y)
{
    int p = blockIdx.x * blockDim.x + threadIdx.x;   // 0 .. BATCH*HW
    if (p >= BATCH * HW) return;
    int b  = p / HW;
    int pp = p - b * HW;
    const float* xb = x + (size_t)b * DIM * HW + pp;
    float s = 0.f, ss = 0.f;
    #pragma unroll 4
    for (int c = 0; c < DIM; c++) {
        float v = xb[(size_t)c * HW];
        s  += v;
        ss += v * v;
    }
    float mu  = s * (1.0f / DIM);
    float var = ss * (1.0f / DIM) - mu * mu;
    float inv = rsqrtf(var + 1e-5f);
    float* yb = y + (size_t)b * DIM * HW + pp;
    #pragma unroll 4
    for (int c = 0; c < DIM; c++) {
        float v = xb[(size_t)c * HW];
        yb[(size_t)c * HW] = (v - mu) * inv * w[c] + bia[c];
    }
}

// ---------------------------------------------------------------------------
// SGEMM: Y[b] = W(MxK) * X[b](KxN) (+ R[b]), N = HW (multiple of 128)
// 128x128 block tile, K-tile 8, 256 threads, 8x8 per-thread micro-tile
// ---------------------------------------------------------------------------
__global__ __launch_bounds__(256, 2)
void sgemm_kernel(const float* __restrict__ W,
                  const float* __restrict__ X,
                  const float* __restrict__ R,   // may be nullptr
                  float* __restrict__ Y,
                  int M, int K, int N)
{
    __shared__ float As[8][128];
    __shared__ float Bs[8][128];

    int tid = threadIdx.x;
    int tx = tid & 15;
    int ty = tid >> 4;
    int tn0 = blockIdx.x * 128;
    int tm0 = blockIdx.y * 128;
    size_t b = blockIdx.z;
    const float* Xb = X + b * (size_t)K * N;

    float acc[8][8];
    #pragma unroll
    for (int i = 0; i < 8; i++)
        #pragma unroll
        for (int j = 0; j < 8; j++) acc[i][j] = 0.f;

    int bk = tid >> 5;            // 0..7
    int bn = (tid & 31) * 4;      // 0..124

    for (int k0 = 0; k0 < K; k0 += 8) {
        // load A tile (128 x 8) transposed into As[k][m]
        #pragma unroll
        for (int i = 0; i < 4; i++) {
            int e  = tid * 4 + i;
            int m  = e >> 3;
            int kk = e & 7;
            int gm = tm0 + m, gk = k0 + kk;
            As[kk][m] = (gm < M && gk < K) ? W[(size_t)gm * K + gk] : 0.f;
        }
        // load B tile (8 x 128)
        {
            int gk = k0 + bk;
            float4 v = make_float4(0.f, 0.f, 0.f, 0.f);
            if (gk < K)
                v = *reinterpret_cast<const float4*>(&Xb[(size_t)gk * N + tn0 + bn]);
            *reinterpret_cast<float4*>(&Bs[bk][bn]) = v;
        }
        __syncthreads();

        #pragma unroll
        for (int kk = 0; kk < 8; kk++) {
            float a[8], bb[8];
            #pragma unroll
            for (int i = 0; i < 8; i++) a[i]  = As[kk][ty * 8 + i];
            #pragma unroll
            for (int j = 0; j < 8; j++) bb[j] = Bs[kk][tx * 8 + j];
            #pragma unroll
            for (int i = 0; i < 8; i++)
                #pragma unroll
                for (int j = 0; j < 8; j++)
                    acc[i][j] += a[i] * bb[j];
        }
        __syncthreads();
    }

    float* Yb = Y + b * (size_t)M * N;
    const float* Rb = R ? (R + b * (size_t)M * N) : nullptr;
    #pragma unroll
    for (int i = 0; i < 8; i++) {
        int gm = tm0 + ty * 8 + i;
        if (gm >= M) continue;
        #pragma unroll
        for (int j = 0; j < 8; j++) {
            int gn = tn0 + tx * 8 + j;
            float v = acc[i][j];
            if (Rb) v += Rb[(size_t)gm * N + gn];
            Yb[(size_t)gm * N + gn] = v;
        }
    }
}

// ---------------------------------------------------------------------------
// Depthwise 3x3 conv, padding SAME
// ---------------------------------------------------------------------------
__global__ void dwconv3_kernel(const float* __restrict__ x,
                               const float* __restrict__ w,
                               float* __restrict__ y, int Cn)
{
    int p = blockIdx.x * blockDim.x + threadIdx.x;  // 0..HW
    int c = blockIdx.y;
    int b = blockIdx.z;
    if (p >= HW) return;
    int yy = p >> 7;
    int xx = p & 127;
    const float* xb = x + ((size_t)b * Cn + c) * HW;
    const float* wc = w + c * 9;
    float acc = 0.f;
    #pragma unroll
    for (int dy = -1; dy <= 1; dy++) {
        int iy = yy + dy;
        if (iy < 0 || iy >= HGT) continue;
        #pragma unroll
        for (int dx = -1; dx <= 1; dx++) {
            int ix = xx + dx;
            if (ix < 0 || ix >= WID) continue;
            acc += xb[iy * WID + ix] * wc[(dy + 1) * 3 + (dx + 1)];
        }
    }
    y[((size_t)b * Cn + c) * HW + p] = acc;
}

// ---------------------------------------------------------------------------
// L2-normalize each (b, channel) row of q/k over HW (channels 0..383 of qkv2)
// ---------------------------------------------------------------------------
__global__ void l2norm_kernel(float* __restrict__ qkv2)
{
    int c = blockIdx.x;   // 0..383
    int b = blockIdx.y;
    float* row = qkv2 + ((size_t)b * 3 * DIM + c) * HW;
    __shared__ float red[256];
    float ss = 0.f;
    for (int i = threadIdx.x; i < HW; i += 256) {
        float v = row[i];
        ss += v * v;
    }
    red[threadIdx.x] = ss;
    __syncthreads();
    for (int s = 128; s > 0; s >>= 1) {
        if (threadIdx.x < s) red[threadIdx.x] += red[threadIdx.x + s];
        __syncthreads();
    }
    float inv = 1.0f / fmaxf(sqrtf(red[0]), 1e-12f);
    for (int i = threadIdx.x; i < HW; i += 256)
        row[i] *= inv;
}

// ---------------------------------------------------------------------------
// q @ k^T split-K partials: pattn[b][h][split][d*24+c]
// ---------------------------------------------------------------------------
__global__ void attn_qk_kernel(const float* __restrict__ qkv2,
                               float* __restrict__ pattn)
{
    int split = blockIdx.x;   // 0..31
    int h = blockIdx.y;
    int b = blockIdx.z;
    const float* qb = qkv2 + ((size_t)b * 3 * DIM + h * HEADDIM) * HW;
    const float* kb = qkv2 + ((size_t)b * 3 * DIM + DIM + h * HEADDIM) * HW;

    __shared__ float sq[HEADDIM][128];
    __shared__ float sk[HEADDIM][128];
    int tid = threadIdx.x;   // 256

    float acc0 = 0.f, acc1 = 0.f, acc2 = 0.f;
    int e1 = tid, e2 = tid + 256, e3 = tid + 512;
    int d1 = e1 / 24, c1 = e1 % 24;
    int d2 = e2 / 24, c2 = e2 % 24;
    int d3 = (e3 < 576) ? e3 / 24 : 0, c3 = (e3 < 576) ? e3 % 24 : 0;

    int e0 = split * (HW / NSPLIT);   // 512 elems per split
    for (int eo = 0; eo < HW / NSPLIT; eo += 128) {
        for (int t = tid; t < HEADDIM * 128; t += 256) {
            int r = t >> 7, ee = t & 127;
            sq[r][ee] = qb[(size_t)r * HW + e0 + eo + ee];
            sk[r][ee] = kb[(size_t)r * HW + e0 + eo + ee];
        }
        __syncthreads();
        #pragma unroll 4
        for (int x = 0; x < 128; x++) {
            acc0 += sq[d1][x] * sk[c1][x];
            acc1 += sq[d2][x] * sk[c2][x];
            acc2 += sq[d3][x] * sk[c3][x];
        }
        __syncthreads();
    }
    size_t base = (((size_t)(b * HEADS + h) * NSPLIT) + split) * 576;
    pattn[base + e1] = acc0;
    pattn[base + e2] = acc1;
    if (e3 < 576) pattn[base + e3] = acc2;
}

// ---------------------------------------------------------------------------
// reduce partials + temperature + softmax over last dim (24); one warp/row
// ---------------------------------------------------------------------------
__global__ void attn_softmax_kernel(const float* __restrict__ pattn,
                                    const float* __restrict__ temp,
                                    float* __restrict__ attn)
{
    int warp = (blockIdx.x * blockDim.x + threadIdx.x) >> 5;
    int lane = threadIdx.x & 31;
    if (warp >= BATCH * HEADS * HEADDIM) return;
    int d  = warp % HEADDIM;
    int bh = warp / HEADDIM;
    int h  = bh % HEADS;

    float v;
    if (lane < 24) {
        float s = 0.f;
        for (int sp = 0; sp < NSPLIT; sp++)
            s += pattn[((size_t)bh * NSPLIT + sp) * 576 + d * 24 + lane];
        v = s * temp[h];
    } else {
        v = -1e30f;
    }
    float m = v;
    #pragma unroll
    for (int o = 16; o > 0; o >>= 1) m = fmaxf(m, __shfl_xor_sync(0xffffffffu, m, o));
    float ev = (lane < 24) ? expf(v - m) : 0.f;
    float s = ev;
    #pragma unroll
    for (int o = 16; o > 0; o >>= 1) s += __shfl_xor_sync(0xffffffffu, s, o);
    if (lane < 24)
        attn[(size_t)bh * 576 + d * 24 + lane] = ev / s;
}

// ---------------------------------------------------------------------------
// out[b, h*24+d, e] = sum_c attn[b,h,d,c] * v[b,h,c,e]
// ---------------------------------------------------------------------------
__global__ void attn_v_kernel(const float* __restrict__ qkv2,
                              const float* __restrict__ attn,
                              float* __restrict__ out)
{
    int h = blockIdx.y;
    int b = blockIdx.z;
    int e = blockIdx.x * 256 + threadIdx.x;

    __shared__ float sa[576];
    for (int t = threadIdx.x; t < 576; t += 256)
        sa[t] = attn[(size_t)(b * HEADS + h) * 576 + t];
    __syncthreads();

    const float* vb = qkv2 + ((size_t)b * 3 * DIM + 2 * DIM + h * HEADDIM) * HW;
    float acc[HEADDIM];
    #pragma unroll
    for (int d = 0; d < HEADDIM; d++) acc[d] = 0.f;
    for (int c = 0; c < HEADDIM; c++) {
        float vv = vb[(size_t)c * HW + e];
        #pragma unroll
        for (int d = 0; d < HEADDIM; d++)
            acc[d] += sa[d * 24 + c] * vv;
    }
    float* ob = out + ((size_t)b * DIM + h * HEADDIM) * HW;
    #pragma unroll
    for (int d = 0; d < HEADDIM; d++)
        ob[(size_t)d * HW + e] = acc[d];
}

// ---------------------------------------------------------------------------
// GEGLU gate: g = gelu_exact(h2[:,0:510]) * h2[:,510:1020]
// ---------------------------------------------------------------------------
__global__ void geglu_kernel(const float* __restrict__ h2,
                             float* __restrict__ g)
{
    size_t i = (size_t)blockIdx.x * blockDim.x + threadIdx.x;
    size_t total = (size_t)BATCH * HIDDEN * HW;
    if (i >= total) return;
    size_t per_b = (size_t)HIDDEN * HW;
    size_t b = i / per_b;
    size_t r = i - b * per_b;
    const float* hb = h2 + b * (size_t)2 * HIDDEN * HW;
    float x1 = hb[r];
    float x2 = hb[(size_t)HIDDEN * HW + r];
    float ge = 0.5f * x1 * (1.0f + erff(x1 * 0.70710678118654752f));
    g[i] = ge * x2;
}

// ---------------------------------------------------------------------------
// host launch
// ---------------------------------------------------------------------------
extern "C" void kernel_launch(void* const* d_in, const int* in_sizes, int n_in,
                              void* d_out, int out_size)
{
    (void)in_sizes; (void)n_in; (void)out_size;
    const float* x        = (const float*)d_in[0];
    const float* temp     = (const float*)d_in[1];
    const float* ln1_w    = (const float*)d_in[2];
    const float* ln1_b    = (const float*)d_in[3];
    const float* ln2_w    = (const float*)d_in[4];
    const float* ln2_b    = (const float*)d_in[5];
    const float* w_qkv    = (const float*)d_in[6];
    const float* w_qkv_dw = (const float*)d_in[7];
    const float* w_proj   = (const float*)d_in[8];
    const float* w_in     = (const float*)d_in[9];
    const float* w_dw     = (const float*)d_in[10];
    const float* w_out    = (const float*)d_in[11];
    float* out = (float*)d_out;

    float* pool = nullptr;
    cudaGetSymbolAddress((void**)&pool, g_pool);

    float* xn      = pool + OF_XN;
    float* qkv     = pool + OF_QKV;
    float* qkv2    = pool + OF_QKV2;
    float* attnout = pool + OF_ATTNOUT;
    float* ybuf    = pool + OF_Y;
    float* h1      = pool + OF_H1;
    float* h2      = pool + OF_H2;
    float* g       = pool + OF_G;
    float* pattn   = pool + OF_PATTN;
    float* attn    = pool + OF_ATTN;

    // ---- attention branch ----
    ln_chan_kernel<<<(BATCH * HW + 255) / 256, 256>>>(x, ln1_w, ln1_b, xn);

    {   // qkv = W_qkv * xn  (M=576, K=192)
        dim3 grid(HW / 128, (3 * DIM + 127) / 128, BATCH);
        sgemm_kernel<<<grid, 256>>>(w_qkv, xn, nullptr, qkv, 3 * DIM, DIM, HW);
    }
    {   // depthwise 3x3 on 576 channels
        dim3 grid(HW / 256, 3 * DIM, BATCH);
        dwconv3_kernel<<<grid, 256>>>(qkv, w_qkv_dw, qkv2, 3 * DIM);
    }
    {   // l2-normalize q and k rows (channels 0..383) in place
        dim3 grid(2 * DIM, BATCH);
        l2norm_kernel<<<grid, 256>>>(qkv2);
    }
    {   // q @ k^T partials
        dim3 grid(NSPLIT, HEADS, BATCH);
        attn_qk_kernel<<<grid, 256>>>(qkv2, pattn);
    }
    {   // reduce + softmax
        int warps = BATCH * HEADS * HEADDIM;          // 768
        attn_softmax_kernel<<<(warps * 32 + 255) / 256, 256>>>(pattn, temp, attn);
    }
    {   // attn @ v
        dim3 grid(HW / 256, HEADS, BATCH);
        attn_v_kernel<<<grid, 256>>>(qkv2, attn, attnout);
    }
    {   // proj + residual: y = W_proj * attnout + x  (M=192, K=192)
        dim3 grid(HW / 128, (DIM + 127) / 128, BATCH);
        sgemm_kernel<<<grid, 256>>>(w_proj, attnout, x, ybuf, DIM, DIM, HW);
    }

    // ---- FFN branch ----
    ln_chan_kernel<<<(BATCH * HW + 255) / 256, 256>>>(ybuf, ln2_w, ln2_b, xn);

    {   // h1 = W_in * xn  (M=1020, K=192)
        dim3 grid(HW / 128, (2 * HIDDEN + 127) / 128, BATCH);
        sgemm_kernel<<<grid, 256>>>(w_in, xn, nullptr, h1, 2 * HIDDEN, DIM, HW);
    }
    {   // depthwise 3x3 on 1020 channels
        dim3 grid(HW / 256, 2 * HIDDEN, BATCH);
        dwconv3_kernel<<<grid, 256>>>(h1, w_dw, h2, 2 * HIDDEN);
    }
    {   // geglu gate
        size_t total = (size_t)BATCH * HIDDEN * HW;
        geglu_kernel<<<(unsigned)((total + 255) / 256), 256>>>(h2, g);
    }
    {   // out = W_out * g + y  (M=192, K=510)
        dim3 grid(HW / 128, (DIM + 127) / 128, BATCH);
        sgemm_kernel<<<grid, 256>>>(w_out, g, ybuf, out, DIM, HIDDEN, HW);
    }
}

// round 2
// speedup vs baseline: 2.0984x; 2.0984x over previous
#include <cuda_runtime.h>
#include <cuda_bf16.h>
#include <math.h>
#include <stdint.h>

// ---------------------------------------------------------------------------
// Problem constants
// ---------------------------------------------------------------------------
#define BATCH   4
#define DIM     192
#define HEADS   8
#define HEADDIM 24
#define HIDDEN  510
#define HGT     128
#define WID     128
#define HW      16384
#define NSPLIT  32

// scratch pool layout (floats)
#define N_XN      ((size_t)BATCH * DIM * HW)
#define N_H       ((size_t)BATCH * 2 * HIDDEN * HW)
#define N_G       ((size_t)BATCH * HIDDEN * HW)

#define OF_XN       ((size_t)0)
#define OF_QKV      (OF_XN + N_XN)
#define OF_QKV2     (OF_QKV + 3 * N_XN)
#define OF_ATTNOUT  (OF_QKV2 + 3 * N_XN)
#define OF_Y        (OF_ATTNOUT + N_XN)
#define OF_H1       (OF_Y + N_XN)
#define OF_G        (OF_H1 + N_H)
#define OF_PATTN    (OF_G + N_G)
#define OF_ATTN     (OF_PATTN + (size_t)BATCH * HEADS * NSPLIT * 576)
#define OF_INV      (OF_ATTN + (size_t)BATCH * HEADS * 576)
#define OF_WP       (OF_INV + (size_t)BATCH * 2 * DIM)
#define POOL_TOTAL  (OF_WP + (size_t)192 * 512)

__device__ __align__(128) float g_pool[POOL_TOTAL];

// ---------------------------------------------------------------------------
// packed f32x2 helpers
// ---------------------------------------------------------------------------
__device__ __forceinline__ uint64_t pack2(float x) {
    uint64_t r;
    asm("mov.b64 %0, {%1, %1};" : "=l"(r) : "f"(x));
    return r;
}
__device__ __forceinline__ void ffma2(uint64_t& d, uint64_t a, uint64_t b) {
    asm("fma.rn.f32x2 %0, %1, %2, %0;" : "+l"(d) : "l"(a), "l"(b));
}
__device__ __forceinline__ float2 unpack2(uint64_t v) {
    float2 f;
    asm("mov.b64 {%0, %1}, %2;" : "=f"(f.x), "=f"(f.y) : "l"(v));
    return f;
}

// ---------------------------------------------------------------------------
// Channel LayerNorm over NCHW channel dim (192), per pixel
// ---------------------------------------------------------------------------
__global__ void ln_chan_kernel(const float* __restrict__ x,
                               const float* __restrict__ w,
                               const float* __restrict__ bia,
                               float* __restrict__ y)
{
    int p = blockIdx.x * blockDim.x + threadIdx.x;
    if (p >= BATCH * HW) return;
    int b  = p / HW;
    int pp = p - b * HW;
    const float* xb = x + (size_t)b * DIM * HW + pp;
    float s = 0.f, ss = 0.f;
    #pragma unroll 4
    for (int c = 0; c < DIM; c++) {
        float v = xb[(size_t)c * HW];
        s  += v;
        ss += v * v;
    }
    float mu  = s * (1.0f / DIM);
    float var = ss * (1.0f / DIM) - mu * mu;
    float inv = rsqrtf(var + 1e-5f);
    float* yb = y + (size_t)b * DIM * HW + pp;
    #pragma unroll 4
    for (int c = 0; c < DIM; c++) {
        float v = xb[(size_t)c * HW];
        yb[(size_t)c * HW] = (v - mu) * inv * w[c] + bia[c];
    }
}

// ---------------------------------------------------------------------------
// SGEMM with fma.rn.f32x2 (FFMA2): Y[b] = W(MxK) * X[b](Kx x N) (+ R[b])
// K = loop extent (mult of 16, W padded to K cols), Kx = valid rows of X
// 128x128 block tile, BK=16, 256 threads, 8x8 micro-tile, double-buffered
// ---------------------------------------------------------------------------
__global__ __launch_bounds__(256, 2)
void sgemm2_kernel(const float* __restrict__ W,
                   const float* __restrict__ X,
                   const float* __restrict__ R,
                   float* __restrict__ Y,
                   int M, int K, int Kx, int N)
{
    __shared__ float As[2][16][128];
    __shared__ float Bs[2][16][128];

    int tid = threadIdx.x;
    int tx = tid & 15;
    int ty = tid >> 4;
    int tn0 = blockIdx.x * 128;
    int tm0 = blockIdx.y * 128;
    const float* Xb = X + (size_t)blockIdx.z * Kx * N;

    // A loads: m = tid>>1 (0..127), k base = (tid&1)*8, two float4 along K
    int am = tid >> 1, ak = (tid & 1) * 8;
    // B loads: k = tid>>4 (0..15), n base = (tid&15)*8, two float4 along N
    int bk = tid >> 4, bn = (tid & 15) * 8;

    float4 pa0, pa1, pb0, pb1;

    uint64_t acc[8][4];
    #pragma unroll
    for (int i = 0; i < 8; i++)
        #pragma unroll
        for (int j = 0; j < 4; j++) acc[i][j] = 0ull;

    const int nt = K / 16;

    // prefetch tile 0
    {
        int gm = tm0 + am;
        if (gm < M) {
            const float* p = &W[(size_t)gm * K + ak];
            pa0 = *(const float4*)p;
            pa1 = *(const float4*)(p + 4);
        } else {
            pa0 = make_float4(0.f, 0.f, 0.f, 0.f);
            pa1 = pa0;
        }
        if (bk < Kx) {
            const float* p = &Xb[(size_t)bk * N + tn0 + bn];
            pb0 = *(const float4*)p;
            pb1 = *(const float4*)(p + 4);
        } else {
            pb0 = make_float4(0.f, 0.f, 0.f, 0.f);
            pb1 = pb0;
        }
    }
    // store to buffer 0
    {
        As[0][ak + 0][am] = pa0.x; As[0][ak + 1][am] = pa0.y;
        As[0][ak + 2][am] = pa0.z; As[0][ak + 3][am] = pa0.w;
        As[0][ak + 4][am] = pa1.x; As[0][ak + 5][am] = pa1.y;
        As[0][ak + 6][am] = pa1.z; As[0][ak + 7][am] = pa1.w;
        *(float4*)&Bs[0][bk][bn]     = pb0;
        *(float4*)&Bs[0][bk][bn + 4] = pb1;
    }
    __syncthreads();

    for (int t = 0; t < nt; t++) {
        int cur = t & 1;
        if (t + 1 < nt) {
            int k0 = (t + 1) * 16;
            int gm = tm0 + am;
            if (gm < M) {
                const float* p = &W[(size_t)gm * K + k0 + ak];
                pa0 = *(const float4*)p;
                pa1 = *(const float4*)(p + 4);
            } else {
                pa0 = make_float4(0.f, 0.f, 0.f, 0.f);
                pa1 = pa0;
            }
            int gk = k0 + bk;
            if (gk < Kx) {
                const float* p = &Xb[(size_t)gk * N + tn0 + bn];
                pb0 = *(const float4*)p;
                pb1 = *(const float4*)(p + 4);
            } else {
                pb0 = make_float4(0.f, 0.f, 0.f, 0.f);
                pb1 = pb0;
            }
        }

        #pragma unroll
        for (int kk = 0; kk < 16; kk++) {
            float4 a0 = *(const float4*)&As[cur][kk][ty * 8];
            float4 a1 = *(const float4*)&As[cur][kk][ty * 8 + 4];
            ulonglong2 q0 = *(const ulonglong2*)&Bs[cur][kk][tx * 8];
            ulonglong2 q1 = *(const ulonglong2*)&Bs[cur][kk][tx * 8 + 4];
            uint64_t bp[4] = {q0.x, q0.y, q1.x, q1.y};
            float av[8] = {a0.x, a0.y, a0.z, a0.w, a1.x, a1.y, a1.z, a1.w};
            #pragma unroll
            for (int i = 0; i < 8; i++) {
                uint64_t ap = pack2(av[i]);
                #pragma unroll
                for (int j = 0; j < 4; j++)
                    ffma2(acc[i][j], ap, bp[j]);
            }
        }

        if (t + 1 < nt) {
            int nxt = cur ^ 1;
            As[nxt][ak + 0][am] = pa0.x; As[nxt][ak + 1][am] = pa0.y;
            As[nxt][ak + 2][am] = pa0.z; As[nxt][ak + 3][am] = pa0.w;
            As[nxt][ak + 4][am] = pa1.x; As[nxt][ak + 5][am] = pa1.y;
            As[nxt][ak + 6][am] = pa1.z; As[nxt][ak + 7][am] = pa1.w;
            *(float4*)&Bs[nxt][bk][bn]     = pb0;
            *(float4*)&Bs[nxt][bk][bn + 4] = pb1;
            __syncthreads();
        }
    }

    float* Yb = Y + (size_t)blockIdx.z * M * N;
    const float* Rb = R ? (R + (size_t)blockIdx.z * M * N) : nullptr;
    #pragma unroll
    for (int i = 0; i < 8; i++) {
        int gm = tm0 + ty * 8 + i;
        if (gm >= M) continue;
        #pragma unroll
        for (int j = 0; j < 4; j++) {
            float2 v = unpack2(acc[i][j]);
            size_t off = (size_t)gm * N + tn0 + tx * 8 + j * 2;
            if (Rb) { v.x += Rb[off]; v.y += Rb[off + 1]; }
            *(float2*)&Yb[off] = v;
        }
    }
}

// ---------------------------------------------------------------------------
// Depthwise 3x3 conv, padding SAME
// ---------------------------------------------------------------------------
__global__ void dwconv3_kernel(const float* __restrict__ x,
                               const float* __restrict__ w,
                               float* __restrict__ y, int Cn)
{
    int p = blockIdx.x * blockDim.x + threadIdx.x;
    int c = blockIdx.y;
    int b = blockIdx.z;
    if (p >= HW) return;
    int yy = p >> 7;
    int xx = p & 127;
    const float* xb = x + ((size_t)b * Cn + c) * HW;
    const float* wc = w + c * 9;
    float acc = 0.f;
    #pragma unroll
    for (int dy = -1; dy <= 1; dy++) {
        int iy = yy + dy;
        if (iy < 0 || iy >= HGT) continue;
        #pragma unroll
        for (int dx = -1; dx <= 1; dx++) {
            int ix = xx + dx;
            if (ix < 0 || ix >= WID) continue;
            acc += xb[iy * WID + ix] * wc[(dy + 1) * 3 + (dx + 1)];
        }
    }
    y[((size_t)b * Cn + c) * HW + p] = acc;
}

// ---------------------------------------------------------------------------
// Fused dwconv3x3 + GEGLU: g[c] = gelu(conv(h1[c])) * conv(h1[c+HIDDEN])
// ---------------------------------------------------------------------------
__global__ void dwconv_geglu_kernel(const float* __restrict__ h1,
                                    const float* __restrict__ w,
                                    float* __restrict__ g)
{
    int p = blockIdx.x * blockDim.x + threadIdx.x;
    int c = blockIdx.y;          // 0..HIDDEN-1
    int b = blockIdx.z;
    if (p >= HW) return;
    int yy = p >> 7;
    int xx = p & 127;
    const float* x1b = h1 + ((size_t)b * 2 * HIDDEN + c) * HW;
    const float* x2b = x1b + (size_t)HIDDEN * HW;
    const float* w1 = w + c * 9;
    const float* w2 = w + (c + HIDDEN) * 9;
    float a1 = 0.f, a2 = 0.f;
    #pragma unroll
    for (int dy = -1; dy <= 1; dy++) {
        int iy = yy + dy;
        if (iy < 0 || iy >= HGT) continue;
        #pragma unroll
        for (int dx = -1; dx <= 1; dx++) {
            int ix = xx + dx;
            if (ix < 0 || ix >= WID) continue;
            int o = iy * WID + ix;
            int wi = (dy + 1) * 3 + (dx + 1);
            a1 += x1b[o] * w1[wi];
            a2 += x2b[o] * w2[wi];
        }
    }
    float ge = 0.5f * a1 * (1.0f + erff(a1 * 0.70710678118654752f));
    g[((size_t)b * HIDDEN + c) * HW + p] = ge * a2;
}

// ---------------------------------------------------------------------------
// per-row inverse L2 norm for q/k channels (0..383) of qkv2 (read-only)
// ---------------------------------------------------------------------------
__global__ void rownorm_kernel(const float* __restrict__ qkv2,
                               float* __restrict__ invn)
{
    int c = blockIdx.x;   // 0..383
    int b = blockIdx.y;
    const float* row = qkv2 + ((size_t)b * 3 * DIM + c) * HW;
    __shared__ float red[256];
    float ss = 0.f;
    for (int i = threadIdx.x; i < HW; i += 256) {
        float v = row[i];
        ss += v * v;
    }
    red[threadIdx.x] = ss;
    __syncthreads();
    for (int s = 128; s > 0; s >>= 1) {
        if (threadIdx.x < s) red[threadIdx.x] += red[threadIdx.x + s];
        __syncthreads();
    }
    if (threadIdx.x == 0)
        invn[(size_t)b * 2 * DIM + c] = 1.0f / fmaxf(sqrtf(red[0]), 1e-12f);
}

// ---------------------------------------------------------------------------
// q @ k^T split-K partials (unnormalized q,k)
// ---------------------------------------------------------------------------
__global__ void attn_qk_kernel(const float* __restrict__ qkv2,
                               float* __restrict__ pattn)
{
    int split = blockIdx.x;
    int h = blockIdx.y;
    int b = blockIdx.z;
    const float* qb = qkv2 + ((size_t)b * 3 * DIM + h * HEADDIM) * HW;
    const float* kb = qkv2 + ((size_t)b * 3 * DIM + DIM + h * HEADDIM) * HW;

    __shared__ float sq[HEADDIM][128];
    __shared__ float sk[HEADDIM][128];
    int tid = threadIdx.x;

    float acc0 = 0.f, acc1 = 0.f, acc2 = 0.f;
    int e1 = tid, e2 = tid + 256, e3 = tid + 512;
    int d1 = e1 / 24, c1 = e1 % 24;
    int d2 = e2 / 24, c2 = e2 % 24;
    int d3 = (e3 < 576) ? e3 / 24 : 0, c3 = (e3 < 576) ? e3 % 24 : 0;

    int e0 = split * (HW / NSPLIT);
    for (int eo = 0; eo < HW / NSPLIT; eo += 128) {
        for (int t = tid; t < HEADDIM * 128; t += 256) {
            int r = t >> 7, ee = t & 127;
            sq[r][ee] = qb[(size_t)r * HW + e0 + eo + ee];
            sk[r][ee] = kb[(size_t)r * HW + e0 + eo + ee];
        }
        __syncthreads();
        #pragma unroll 4
        for (int x = 0; x < 128; x++) {
            acc0 += sq[d1][x] * sk[c1][x];
            acc1 += sq[d2][x] * sk[c2][x];
            acc2 += sq[d3][x] * sk[c3][x];
        }
        __syncthreads();
    }
    size_t base = (((size_t)(b * HEADS + h) * NSPLIT) + split) * 576;
    pattn[base + e1] = acc0;
    pattn[base + e2] = acc1;
    if (e3 < 576) pattn[base + e3] = acc2;
}

// ---------------------------------------------------------------------------
// reduce partials, apply 1/(|q||k|) and temperature, softmax over 24
// ---------------------------------------------------------------------------
__global__ void attn_softmax_kernel(const float* __restrict__ pattn,
                                    const float* __restrict__ temp,
                                    const float* __restrict__ invn,
                                    float* __restrict__ attn)
{
    int warp = (blockIdx.x * blockDim.x + threadIdx.x) >> 5;
    int lane = threadIdx.x & 31;
    if (warp >= BATCH * HEADS * HEADDIM) return;
    int d  = warp % HEADDIM;
    int bh = warp / HEADDIM;
    int h  = bh % HEADS;
    int b  = bh / HEADS;

    float v;
    if (lane < 24) {
        float s = 0.f;
        for (int sp = 0; sp < NSPLIT; sp++)
            s += pattn[((size_t)bh * NSPLIT + sp) * 576 + d * 24 + lane];
        float iq = invn[(size_t)b * 2 * DIM + h * HEADDIM + d];
        float ik = invn[(size_t)b * 2 * DIM + DIM + h * HEADDIM + lane];
        v = s * iq * ik * temp[h];
    } else {
        v = -1e30f;
    }
    float m = v;
    #pragma unroll
    for (int o = 16; o > 0; o >>= 1) m = fmaxf(m, __shfl_xor_sync(0xffffffffu, m, o));
    float ev = (lane < 24) ? expf(v - m) : 0.f;
    float s = ev;
    #pragma unroll
    for (int o = 16; o > 0; o >>= 1) s += __shfl_xor_sync(0xffffffffu, s, o);
    if (lane < 24)
        attn[(size_t)bh * 576 + d * 24 + lane] = ev / s;
}

// ---------------------------------------------------------------------------
// out[b, h*24+d, e] = sum_c attn[b,h,d,c] * v[b,h,c,e]
// ---------------------------------------------------------------------------
__global__ void attn_v_kernel(const float* __restrict__ qkv2,
                              const float* __restrict__ attn,
                              float* __restrict__ out)
{
    int h = blockIdx.y;
    int b = blockIdx.z;
    int e = blockIdx.x * 256 + threadIdx.x;

    __shared__ float sa[576];
    for (int t = threadIdx.x; t < 576; t += 256)
        sa[t] = attn[(size_t)(b * HEADS + h) * 576 + t];
    __syncthreads();

    const float* vb = qkv2 + ((size_t)b * 3 * DIM + 2 * DIM + h * HEADDIM) * HW;
    float acc[HEADDIM];
    #pragma unroll
    for (int d = 0; d < HEADDIM; d++) acc[d] = 0.f;
    for (int c = 0; c < HEADDIM; c++) {
        float vv = vb[(size_t)c * HW + e];
        #pragma unroll
        for (int d = 0; d < HEADDIM; d++)
            acc[d] += sa[d * 24 + c] * vv;
    }
    float* ob = out + ((size_t)b * DIM + h * HEADDIM) * HW;
    #pragma unroll
    for (int d = 0; d < HEADDIM; d++)
        ob[(size_t)d * HW + e] = acc[d];
}

// ---------------------------------------------------------------------------
// pad w_out (192x510) to 192x512 with zeros
// ---------------------------------------------------------------------------
__global__ void pad_wout_kernel(const float* __restrict__ w,
                                float* __restrict__ wp)
{
    int i = blockIdx.x * blockDim.x + threadIdx.x;
    if (i >= 192 * 512) return;
    int m = i >> 9, k = i & 511;
    wp[i] = (k < HIDDEN) ? w[m * HIDDEN + k] : 0.f;
}

// ---------------------------------------------------------------------------
// host launch
// ---------------------------------------------------------------------------
extern "C" void kernel_launch(void* const* d_in, const int* in_sizes, int n_in,
                              void* d_out, int out_size)
{
    (void)in_sizes; (void)n_in; (void)out_size;
    const float* x        = (const float*)d_in[0];
    const float* temp     = (const float*)d_in[1];
    const float* ln1_w    = (const float*)d_in[2];
    const float* ln1_b    = (const float*)d_in[3];
    const float* ln2_w    = (const float*)d_in[4];
    const float* ln2_b    = (const float*)d_in[5];
    const float* w_qkv    = (const float*)d_in[6];
    const float* w_qkv_dw = (const float*)d_in[7];
    const float* w_proj   = (const float*)d_in[8];
    const float* w_in     = (const float*)d_in[9];
    const float* w_dw     = (const float*)d_in[10];
    const float* w_out    = (const float*)d_in[11];
    float* out = (float*)d_out;

    float* pool = nullptr;
    cudaGetSymbolAddress((void**)&pool, g_pool);

    float* xn      = pool + OF_XN;
    float* qkv     = pool + OF_QKV;
    float* qkv2    = pool + OF_QKV2;
    float* attnout = pool + OF_ATTNOUT;
    float* ybuf    = pool + OF_Y;
    float* h1      = pool + OF_H1;
    float* g       = pool + OF_G;
    float* pattn   = pool + OF_PATTN;
    float* attn    = pool + OF_ATTN;
    float* invn    = pool + OF_INV;
    float* wp      = pool + OF_WP;

    pad_wout_kernel<<<(192 * 512 + 255) / 256, 256>>>(w_out, wp);

    // ---- attention branch ----
    ln_chan_kernel<<<(BATCH * HW + 255) / 256, 256>>>(x, ln1_w, ln1_b, xn);

    {   // qkv = W_qkv * xn  (M=576, K=192)
        dim3 grid(HW / 128, (3 * DIM + 127) / 128, BATCH);
        sgemm2_kernel<<<grid, 256>>>(w_qkv, xn, nullptr, qkv, 3 * DIM, DIM, DIM, HW);
    }
    {   // depthwise 3x3 on 576 channels
        dim3 grid(HW / 256, 3 * DIM, BATCH);
        dwconv3_kernel<<<grid, 256>>>(qkv, w_qkv_dw, qkv2, 3 * DIM);
    }
    {   // inverse norms of q,k rows
        dim3 grid(2 * DIM, BATCH);
        rownorm_kernel<<<grid, 256>>>(qkv2, invn);
    }
    {   // q @ k^T partials
        dim3 grid(NSPLIT, HEADS, BATCH);
        attn_qk_kernel<<<grid, 256>>>(qkv2, pattn);
    }
    {   // reduce + scale + softmax
        int warps = BATCH * HEADS * HEADDIM;
        attn_softmax_kernel<<<(warps * 32 + 255) / 256, 256>>>(pattn, temp, invn, attn);
    }
    {   // attn @ v
        dim3 grid(HW / 256, HEADS, BATCH);
        attn_v_kernel<<<grid, 256>>>(qkv2, attn, attnout);
    }
    {   // proj + residual: y = W_proj * attnout + x
        dim3 grid(HW / 128, (DIM + 127) / 128, BATCH);
        sgemm2_kernel<<<grid, 256>>>(w_proj, attnout, x, ybuf, DIM, DIM, DIM, HW);
    }

    // ---- FFN branch ----
    ln_chan_kernel<<<(BATCH * HW + 255) / 256, 256>>>(ybuf, ln2_w, ln2_b, xn);

    {   // h1 = W_in * xn  (M=1020, K=192)
        dim3 grid(HW / 128, (2 * HIDDEN + 127) / 128, BATCH);
        sgemm2_kernel<<<grid, 256>>>(w_in, xn, nullptr, h1, 2 * HIDDEN, DIM, DIM, HW);
    }
    {   // fused dwconv + geglu -> g
        dim3 grid(HW / 256, HIDDEN, BATCH);
        dwconv_geglu_kernel<<<grid, 256>>>(h1, w_dw, g);
    }
    {   // out = W_out * g + y  (M=192, K=510 padded to 512)
        dim3 grid(HW / 128, (DIM + 127) / 128, BATCH);
        sgemm2_kernel<<<grid, 256>>>(wp, g, ybuf, out, DIM, 512, HIDDEN, HW);
    }
}

// round 3
// speedup vs baseline: 3.8650x; 1.8419x over previous
#include <cuda_runtime.h>
#include <cuda_bf16.h>
#include <math.h>
#include <stdint.h>

// ---------------------------------------------------------------------------
// Problem constants
// ---------------------------------------------------------------------------
#define BATCH   4
#define DIM     192
#define HEADS   8
#define HEADDIM 24
#define HIDDEN  510
#define HGT     128
#define WID     128
#define HW      16384
#define NSPLIT  32

// scratch pool layout (floats)
#define N_XN      ((size_t)BATCH * DIM * HW)
#define N_H       ((size_t)BATCH * 2 * HIDDEN * HW)
#define N_G       ((size_t)BATCH * HIDDEN * HW)

#define OF_XN       ((size_t)0)
#define OF_QKV      (OF_XN + N_XN)
#define OF_QKV2     (OF_QKV + 3 * N_XN)
#define OF_ATTNOUT  (OF_QKV2 + 3 * N_XN)
#define OF_Y        (OF_ATTNOUT + N_XN)
#define OF_H1       (OF_Y + N_XN)
#define OF_G        (OF_H1 + N_H)
#define OF_PATTN    (OF_G + N_G)
#define OF_ATTN     (OF_PATTN + (size_t)BATCH * HEADS * NSPLIT * 576)
#define OF_INV      (OF_ATTN + (size_t)BATCH * HEADS * 576)
#define OF_WP       (OF_INV + (size_t)BATCH * 2 * DIM)
#define POOL_TOTAL  (OF_WP + (size_t)192 * 512)

__device__ __align__(128) float g_pool[POOL_TOTAL];

// ---------------------------------------------------------------------------
// tf32 helpers
// ---------------------------------------------------------------------------
__device__ __forceinline__ uint32_t f2tf(float f) {
    uint32_t r;
    asm("cvt.rna.tf32.f32 %0, %1;" : "=r"(r) : "f"(f));
    return r;
}
__device__ __forceinline__ void mma_tf32(float* c, const uint32_t* a,
                                         uint32_t b0, uint32_t b1) {
    asm volatile(
        "mma.sync.aligned.m16n8k8.row.col.f32.tf32.tf32.f32 "
        "{%0,%1,%2,%3}, {%4,%5,%6,%7}, {%8,%9}, {%0,%1,%2,%3};"
        : "+f"(c[0]), "+f"(c[1]), "+f"(c[2]), "+f"(c[3])
        : "r"(a[0]), "r"(a[1]), "r"(a[2]), "r"(a[3]), "r"(b0), "r"(b1));
}

// ---------------------------------------------------------------------------
// Channel LayerNorm over NCHW channel dim (192), per pixel
// ---------------------------------------------------------------------------
__global__ void ln_chan_kernel(const float* __restrict__ x,
                               const float* __restrict__ w,
                               const float* __restrict__ bia,
                               float* __restrict__ y)
{
    int p = blockIdx.x * blockDim.x + threadIdx.x;
    if (p >= BATCH * HW) return;
    int b  = p / HW;
    int pp = p - b * HW;
    const float* xb = x + (size_t)b * DIM * HW + pp;
    float s = 0.f, ss = 0.f;
    #pragma unroll 4
    for (int c = 0; c < DIM; c++) {
        float v = xb[(size_t)c * HW];
        s  += v;
        ss += v * v;
    }
    float mu  = s * (1.0f / DIM);
    float var = ss * (1.0f / DIM) - mu * mu;
    float inv = rsqrtf(var + 1e-5f);
    float* yb = y + (size_t)b * DIM * HW + pp;
    #pragma unroll 4
    for (int c = 0; c < DIM; c++) {
        float v = xb[(size_t)c * HW];
        yb[(size_t)c * HW] = (v - mu) * inv * w[c] + bia[c];
    }
}

// ---------------------------------------------------------------------------
// TF32 tensor-core GEMM: Y[b] = W(MxK) * X[b](Kx x N) (+ R[b])
// K mult of 16 (loop extent, W has K cols), Kx = valid rows of X (zero-pad).
// 128x128 block tile, BK=16, 256 threads (8 warps @ 32x64), double-buffered.
// smem row stride 136 words (== 8 mod 32) -> conflict-free fragment loads.
// ---------------------------------------------------------------------------
__global__ __launch_bounds__(256)
void mma_gemm_kernel(const float* __restrict__ W,
                     const float* __restrict__ X,
                     const float* __restrict__ R,
                     float* __restrict__ Y,
                     int M, int K, int Kx, int N)
{
    __shared__ __align__(16) uint32_t As[2][16][136];
    __shared__ __align__(16) uint32_t Bs[2][16][136];

    int tid  = threadIdx.x;
    int lane = tid & 31;
    int warp = tid >> 5;
    int wm = warp & 3;        // 0..3 : 32-row chunk
    int wn = warp >> 2;       // 0..1 : 64-col chunk
    int ar = lane >> 2;       // 0..7
    int ac = lane & 3;        // 0..3

    int tn0 = blockIdx.x * 128;
    int tm0 = blockIdx.y * 128;
    const float* Xb = X + (size_t)blockIdx.z * Kx * N;

    // global load mapping
    int am = tid >> 1, ak = (tid & 1) * 8;      // A: row am, 8 cols from ak
    int bk = tid >> 4, bn = (tid & 15) * 8;     // B: row bk, 8 cols from bn

    float4 pa0, pa1, pb0, pb1;
    float acc[2][8][4];
    #pragma unroll
    for (int i = 0; i < 2; i++)
        #pragma unroll
        for (int j = 0; j < 8; j++)
            #pragma unroll
            for (int l = 0; l < 4; l++) acc[i][j][l] = 0.f;

    const int nt = K / 16;

    // ---- prefetch tile 0
    {
        int gm = tm0 + am;
        if (gm < M) {
            const float* p = &W[(size_t)gm * K + ak];
            pa0 = *(const float4*)p;
            pa1 = *(const float4*)(p + 4);
        } else { pa0 = make_float4(0.f,0.f,0.f,0.f); pa1 = pa0; }
        if (bk < Kx) {
            const float* p = &Xb[(size_t)bk * N + tn0 + bn];
            pb0 = *(const float4*)p;
            pb1 = *(const float4*)(p + 4);
        } else { pb0 = make_float4(0.f,0.f,0.f,0.f); pb1 = pb0; }
    }
    {
        As[0][ak+0][am]=f2tf(pa0.x); As[0][ak+1][am]=f2tf(pa0.y);
        As[0][ak+2][am]=f2tf(pa0.z); As[0][ak+3][am]=f2tf(pa0.w);
        As[0][ak+4][am]=f2tf(pa1.x); As[0][ak+5][am]=f2tf(pa1.y);
        As[0][ak+6][am]=f2tf(pa1.z); As[0][ak+7][am]=f2tf(pa1.w);
        uint4 u0 = {f2tf(pb0.x), f2tf(pb0.y), f2tf(pb0.z), f2tf(pb0.w)};
        uint4 u1 = {f2tf(pb1.x), f2tf(pb1.y), f2tf(pb1.z), f2tf(pb1.w)};
        *(uint4*)&Bs[0][bk][bn]   = u0;
        *(uint4*)&Bs[0][bk][bn+4] = u1;
    }
    __syncthreads();

    for (int t = 0; t < nt; t++) {
        int cur = t & 1;
        if (t + 1 < nt) {
            int k0 = (t + 1) * 16;
            int gm = tm0 + am;
            if (gm < M) {
                const float* p = &W[(size_t)gm * K + k0 + ak];
                pa0 = *(const float4*)p;
                pa1 = *(const float4*)(p + 4);
            } else { pa0 = make_float4(0.f,0.f,0.f,0.f); pa1 = pa0; }
            int gk = k0 + bk;
            if (gk < Kx) {
                const float* p = &Xb[(size_t)gk * N + tn0 + bn];
                pb0 = *(const float4*)p;
                pb1 = *(const float4*)(p + 4);
            } else { pb0 = make_float4(0.f,0.f,0.f,0.f); pb1 = pb0; }
        }

        // ---- compute on buffer cur
        #pragma unroll
        for (int kc = 0; kc < 16; kc += 8) {
            uint32_t af[2][4];
            #pragma unroll
            for (int mi = 0; mi < 2; mi++) {
                int mb = wm * 32 + mi * 16 + ar;
                af[mi][0] = As[cur][kc + ac    ][mb];
                af[mi][1] = As[cur][kc + ac    ][mb + 8];
                af[mi][2] = As[cur][kc + ac + 4][mb];
                af[mi][3] = As[cur][kc + ac + 4][mb + 8];
            }
            int nb0 = wn * 64 + ar;
            #pragma unroll
            for (int ni = 0; ni < 8; ni++) {
                uint32_t b0 = Bs[cur][kc + ac    ][nb0 + ni * 8];
                uint32_t b1 = Bs[cur][kc + ac + 4][nb0 + ni * 8];
                mma_tf32(acc[0][ni], af[0], b0, b1);
                mma_tf32(acc[1][ni], af[1], b0, b1);
            }
        }

        if (t + 1 < nt) {
            int nxt = cur ^ 1;
            As[nxt][ak+0][am]=f2tf(pa0.x); As[nxt][ak+1][am]=f2tf(pa0.y);
            As[nxt][ak+2][am]=f2tf(pa0.z); As[nxt][ak+3][am]=f2tf(pa0.w);
            As[nxt][ak+4][am]=f2tf(pa1.x); As[nxt][ak+5][am]=f2tf(pa1.y);
            As[nxt][ak+6][am]=f2tf(pa1.z); As[nxt][ak+7][am]=f2tf(pa1.w);
            uint4 u0 = {f2tf(pb0.x), f2tf(pb0.y), f2tf(pb0.z), f2tf(pb0.w)};
            uint4 u1 = {f2tf(pb1.x), f2tf(pb1.y), f2tf(pb1.z), f2tf(pb1.w)};
            *(uint4*)&Bs[nxt][bk][bn]   = u0;
            *(uint4*)&Bs[nxt][bk][bn+4] = u1;
            __syncthreads();
        }
    }

    // ---- epilogue
    float* Yb = Y + (size_t)blockIdx.z * M * N;
    const float* Rb = R ? (R + (size_t)blockIdx.z * M * N) : nullptr;
    #pragma unroll
    for (int mi = 0; mi < 2; mi++) {
        #pragma unroll
        for (int ni = 0; ni < 8; ni++) {
            int gm = tm0 + wm * 32 + mi * 16 + ar;
            int gn = tn0 + wn * 64 + ni * 8 + ac * 2;
            if (gm < M) {
                float2 v = {acc[mi][ni][0], acc[mi][ni][1]};
                size_t off = (size_t)gm * N + gn;
                if (Rb) { v.x += Rb[off]; v.y += Rb[off + 1]; }
                *(float2*)&Yb[off] = v;
            }
            if (gm + 8 < M) {
                float2 v = {acc[mi][ni][2], acc[mi][ni][3]};
                size_t off = (size_t)(gm + 8) * N + gn;
                if (Rb) { v.x += Rb[off]; v.y += Rb[off + 1]; }
                *(float2*)&Yb[off] = v;
            }
        }
    }
}

// ---------------------------------------------------------------------------
// Depthwise 3x3, SAME padding; 4 pixels/thread, row-vectorized
// block 256 = 32 threads (x, 4 px each) * 8 rows; grid (HGT/8, C, B)
// ---------------------------------------------------------------------------
__global__ void dwconv3_kernel(const float* __restrict__ x,
                               const float* __restrict__ w,
                               float* __restrict__ y, int Cn)
{
    int tid = threadIdx.x;
    int yy = blockIdx.x * 8 + (tid >> 5);
    int x0 = (tid & 31) * 4;
    int c = blockIdx.y, b = blockIdx.z;
    const float* xb = x + ((size_t)b * Cn + c) * HW;

    float wv[9];
    #pragma unroll
    for (int i = 0; i < 9; i++) wv[i] = __ldg(&w[c * 9 + i]);

    float a0 = 0.f, a1 = 0.f, a2 = 0.f, a3 = 0.f;
    #pragma unroll
    for (int dy = -1; dy <= 1; dy++) {
        int iy = yy + dy;
        if (iy < 0 || iy >= HGT) continue;
        const float* row = xb + iy * WID;
        float l = (x0 > 0) ? __ldg(&row[x0 - 1]) : 0.f;
        float4 m = *(const float4*)&row[x0];
        float r = (x0 + 4 < WID) ? __ldg(&row[x0 + 4]) : 0.f;
        float w0 = wv[(dy + 1) * 3], w1 = wv[(dy + 1) * 3 + 1], w2 = wv[(dy + 1) * 3 + 2];
        a0 += l   * w0 + m.x * w1 + m.y * w2;
        a1 += m.x * w0 + m.y * w1 + m.z * w2;
        a2 += m.y * w0 + m.z * w1 + m.w * w2;
        a3 += m.z * w0 + m.w * w1 + r   * w2;
    }
    float4 o = {a0, a1, a2, a3};
    *(float4*)&y[((size_t)b * Cn + c) * HW + yy * WID + x0] = o;
}

// ---------------------------------------------------------------------------
// Fused dwconv3x3 + GEGLU (4 px/thread)
// ---------------------------------------------------------------------------
__global__ void dwconv_geglu_kernel(const float* __restrict__ h1,
                                    const float* __restrict__ w,
                                    float* __restrict__ g)
{
    int tid = threadIdx.x;
    int yy = blockIdx.x * 8 + (tid >> 5);
    int x0 = (tid & 31) * 4;
    int c = blockIdx.y, b = blockIdx.z;
    const float* x1b = h1 + ((size_t)b * 2 * HIDDEN + c) * HW;
    const float* x2b = x1b + (size_t)HIDDEN * HW;

    float w1v[9], w2v[9];
    #pragma unroll
    for (int i = 0; i < 9; i++) {
        w1v[i] = __ldg(&w[c * 9 + i]);
        w2v[i] = __ldg(&w[(c + HIDDEN) * 9 + i]);
    }

    float p0 = 0.f, p1 = 0.f, p2 = 0.f, p3 = 0.f;
    float q0 = 0.f, q1 = 0.f, q2 = 0.f, q3 = 0.f;
    #pragma unroll
    for (int dy = -1; dy <= 1; dy++) {
        int iy = yy + dy;
        if (iy < 0 || iy >= HGT) continue;
        {
            const float* row = x1b + iy * WID;
            float l = (x0 > 0) ? __ldg(&row[x0 - 1]) : 0.f;
            float4 m = *(const float4*)&row[x0];
            float r = (x0 + 4 < WID) ? __ldg(&row[x0 + 4]) : 0.f;
            float w0 = w1v[(dy+1)*3], w1 = w1v[(dy+1)*3+1], w2 = w1v[(dy+1)*3+2];
            p0 += l   * w0 + m.x * w1 + m.y * w2;
            p1 += m.x * w0 + m.y * w1 + m.z * w2;
            p2 += m.y * w0 + m.z * w1 + m.w * w2;
            p3 += m.z * w0 + m.w * w1 + r   * w2;
        }
        {
            const float* row = x2b + iy * WID;
            float l = (x0 > 0) ? __ldg(&row[x0 - 1]) : 0.f;
            float4 m = *(const float4*)&row[x0];
            float r = (x0 + 4 < WID) ? __ldg(&row[x0 + 4]) : 0.f;
            float w0 = w2v[(dy+1)*3], w1 = w2v[(dy+1)*3+1], w2 = w2v[(dy+1)*3+2];
            q0 += l   * w0 + m.x * w1 + m.y * w2;
            q1 += m.x * w0 + m.y * w1 + m.z * w2;
            q2 += m.y * w0 + m.z * w1 + m.w * w2;
            q3 += m.z * w0 + m.w * w1 + r   * w2;
        }
    }
    const float is2 = 0.70710678118654752f;
    float4 o;
    o.x = 0.5f * p0 * (1.0f + erff(p0 * is2)) * q0;
    o.y = 0.5f * p1 * (1.0f + erff(p1 * is2)) * q1;
    o.z = 0.5f * p2 * (1.0f + erff(p2 * is2)) * q2;
    o.w = 0.5f * p3 * (1.0f + erff(p3 * is2)) * q3;
    *(float4*)&g[((size_t)b * HIDDEN + c) * HW + yy * WID + x0] = o;
}

// ---------------------------------------------------------------------------
// per-row inverse L2 norm for q/k channels (0..383) of qkv2 (read-only)
// ---------------------------------------------------------------------------
__global__ void rownorm_kernel(const float* __restrict__ qkv2,
                               float* __restrict__ invn)
{
    int c = blockIdx.x;
    int b = blockIdx.y;
    const float* row = qkv2 + ((size_t)b * 3 * DIM + c) * HW;
    __shared__ float red[256];
    float ss = 0.f;
    for (int i = threadIdx.x; i < HW; i += 256) {
        float v = row[i];
        ss += v * v;
    }
    red[threadIdx.x] = ss;
    __syncthreads();
    for (int s = 128; s > 0; s >>= 1) {
        if (threadIdx.x < s) red[threadIdx.x] += red[threadIdx.x + s];
        __syncthreads();
    }
    if (threadIdx.x == 0)
        invn[(size_t)b * 2 * DIM + c] = 1.0f / fmaxf(sqrtf(red[0]), 1e-12f);
}

// ---------------------------------------------------------------------------
// q @ k^T split-K partials (unnormalized q,k)
// ---------------------------------------------------------------------------
__global__ void attn_qk_kernel(const float* __restrict__ qkv2,
                               float* __restrict__ pattn)
{
    int split = blockIdx.x;
    int h = blockIdx.y;
    int b = blockIdx.z;
    const float* qb = qkv2 + ((size_t)b * 3 * DIM + h * HEADDIM) * HW;
    const float* kb = qkv2 + ((size_t)b * 3 * DIM + DIM + h * HEADDIM) * HW;

    __shared__ float sq[HEADDIM][128];
    __shared__ float sk[HEADDIM][128];
    int tid = threadIdx.x;

    float acc0 = 0.f, acc1 = 0.f, acc2 = 0.f;
    int e1 = tid, e2 = tid + 256, e3 = tid + 512;
    int d1 = e1 / 24, c1 = e1 % 24;
    int d2 = e2 / 24, c2 = e2 % 24;
    int d3 = (e3 < 576) ? e3 / 24 : 0, c3 = (e3 < 576) ? e3 % 24 : 0;

    int e0 = split * (HW / NSPLIT);
    for (int eo = 0; eo < HW / NSPLIT; eo += 128) {
        for (int t = tid; t < HEADDIM * 128; t += 256) {
            int r = t >> 7, ee = t & 127;
            sq[r][ee] = qb[(size_t)r * HW + e0 + eo + ee];
            sk[r][ee] = kb[(size_t)r * HW + e0 + eo + ee];
        }
        __syncthreads();
        #pragma unroll 4
        for (int x = 0; x < 128; x++) {
            acc0 += sq[d1][x] * sk[c1][x];
            acc1 += sq[d2][x] * sk[c2][x];
            acc2 += sq[d3][x] * sk[c3][x];
        }
        __syncthreads();
    }
    size_t base = (((size_t)(b * HEADS + h) * NSPLIT) + split) * 576;
    pattn[base + e1] = acc0;
    pattn[base + e2] = acc1;
    if (e3 < 576) pattn[base + e3] = acc2;
}

// ---------------------------------------------------------------------------
// reduce partials, apply 1/(|q||k|) and temperature, softmax over 24
// ---------------------------------------------------------------------------
__global__ void attn_softmax_kernel(const float* __restrict__ pattn,
                                    const float* __restrict__ temp,
                                    const float* __restrict__ invn,
                                    float* __restrict__ attn)
{
    int warp = (blockIdx.x * blockDim.x + threadIdx.x) >> 5;
    int lane = threadIdx.x & 31;
    if (warp >= BATCH * HEADS * HEADDIM) return;
    int d  = warp % HEADDIM;
    int bh = warp / HEADDIM;
    int h  = bh % HEADS;
    int b  = bh / HEADS;

    float v;
    if (lane < 24) {
        float s = 0.f;
        for (int sp = 0; sp < NSPLIT; sp++)
            s += pattn[((size_t)bh * NSPLIT + sp) * 576 + d * 24 + lane];
        float iq = invn[(size_t)b * 2 * DIM + h * HEADDIM + d];
        float ik = invn[(size_t)b * 2 * DIM + DIM + h * HEADDIM + lane];
        v = s * iq * ik * temp[h];
    } else {
        v = -1e30f;
    }
    float m = v;
    #pragma unroll
    for (int o = 16; o > 0; o >>= 1) m = fmaxf(m, __shfl_xor_sync(0xffffffffu, m, o));
    float ev = (lane < 24) ? expf(v - m) : 0.f;
    float s = ev;
    #pragma unroll
    for (int o = 16; o > 0; o >>= 1) s += __shfl_xor_sync(0xffffffffu, s, o);
    if (lane < 24)
        attn[(size_t)bh * 576 + d * 24 + lane] = ev / s;
}

// ---------------------------------------------------------------------------
// out[b, h*24+d, e] = sum_c attn[b,h,d,c] * v[b,h,c,e]
// ---------------------------------------------------------------------------
__global__ void attn_v_kernel(const float* __restrict__ qkv2,
                              const float* __restrict__ attn,
                              float* __restrict__ out)
{
    int h = blockIdx.y;
    int b = blockIdx.z;
    int e = blockIdx.x * 256 + threadIdx.x;

    __shared__ float sa[576];
    for (int t = threadIdx.x; t < 576; t += 256)
        sa[t] = attn[(size_t)(b * HEADS + h) * 576 + t];
    __syncthreads();

    const float* vb = qkv2 + ((size_t)b * 3 * DIM + 2 * DIM + h * HEADDIM) * HW;
    float acc[HEADDIM];
    #pragma unroll
    for (int d = 0; d < HEADDIM; d++) acc[d] = 0.f;
    for (int c = 0; c < HEADDIM; c++) {
        float vv = vb[(size_t)c * HW + e];
        #pragma unroll
        for (int d = 0; d < HEADDIM; d++)
            acc[d] += sa[d * 24 + c] * vv;
    }
    float* ob = out + ((size_t)b * DIM + h * HEADDIM) * HW;
    #pragma unroll
    for (int d = 0; d < HEADDIM; d++)
        ob[(size_t)d * HW + e] = acc[d];
}

// ---------------------------------------------------------------------------
// pad w_out (192x510) to 192x512 with zeros
// ---------------------------------------------------------------------------
__global__ void pad_wout_kernel(const float* __restrict__ w,
                                float* __restrict__ wp)
{
    int i = blockIdx.x * blockDim.x + threadIdx.x;
    if (i >= 192 * 512) return;
    int m = i >> 9, k = i & 511;
    wp[i] = (k < HIDDEN) ? w[m * HIDDEN + k] : 0.f;
}

// ---------------------------------------------------------------------------
// host launch
// ---------------------------------------------------------------------------
extern "C" void kernel_launch(void* const* d_in, const int* in_sizes, int n_in,
                              void* d_out, int out_size)
{
    (void)in_sizes; (void)n_in; (void)out_size;
    const float* x        = (const float*)d_in[0];
    const float* temp     = (const float*)d_in[1];
    const float* ln1_w    = (const float*)d_in[2];
    const float* ln1_b    = (const float*)d_in[3];
    const float* ln2_w    = (const float*)d_in[4];
    const float* ln2_b    = (const float*)d_in[5];
    const float* w_qkv    = (const float*)d_in[6];
    const float* w_qkv_dw = (const float*)d_in[7];
    const float* w_proj   = (const float*)d_in[8];
    const float* w_in     = (const float*)d_in[9];
    const float* w_dw     = (const float*)d_in[10];
    const float* w_out    = (const float*)d_in[11];
    float* out = (float*)d_out;

    float* pool = nullptr;
    cudaGetSymbolAddress((void**)&pool, g_pool);

    float* xn      = pool + OF_XN;
    float* qkv     = pool + OF_QKV;
    float* qkv2    = pool + OF_QKV2;
    float* attnout = pool + OF_ATTNOUT;
    float* ybuf    = pool + OF_Y;
    float* h1      = pool + OF_H1;
    float* g       = pool + OF_G;
    float* pattn   = pool + OF_PATTN;
    float* attn    = pool + OF_ATTN;
    float* invn    = pool + OF_INV;
    float* wp      = pool + OF_WP;

    pad_wout_kernel<<<(192 * 512 + 255) / 256, 256>>>(w_out, wp);

    // ---- attention branch ----
    ln_chan_kernel<<<(BATCH * HW + 255) / 256, 256>>>(x, ln1_w, ln1_b, xn);

    {   // qkv = W_qkv * xn  (M=576, K=192)
        dim3 grid(HW / 128, (3 * DIM + 127) / 128, BATCH);
        mma_gemm_kernel<<<grid, 256>>>(w_qkv, xn, nullptr, qkv, 3 * DIM, DIM, DIM, HW);
    }
    {   // depthwise 3x3 on 576 channels
        dim3 grid(HGT / 8, 3 * DIM, BATCH);
        dwconv3_kernel<<<grid, 256>>>(qkv, w_qkv_dw, qkv2, 3 * DIM);
    }
    {   // inverse norms of q,k rows
        dim3 grid(2 * DIM, BATCH);
        rownorm_kernel<<<grid, 256>>>(qkv2, invn);
    }
    {   // q @ k^T partials
        dim3 grid(NSPLIT, HEADS, BATCH);
        attn_qk_kernel<<<grid, 256>>>(qkv2, pattn);
    }
    {   // reduce + scale + softmax
        int warps = BATCH * HEADS * HEADDIM;
        attn_softmax_kernel<<<(warps * 32 + 255) / 256, 256>>>(pattn, temp, invn, attn);
    }
    {   // attn @ v
        dim3 grid(HW / 256, HEADS, BATCH);
        attn_v_kernel<<<grid, 256>>>(qkv2, attn, attnout);
    }
    {   // proj + residual: y = W_proj * attnout + x
        dim3 grid(HW / 128, (DIM + 127) / 128, BATCH);
        mma_gemm_kernel<<<grid, 256>>>(w_proj, attnout, x, ybuf, DIM, DIM, DIM, HW);
    }

    // ---- FFN branch ----
    ln_chan_kernel<<<(BATCH * HW + 255) / 256, 256>>>(ybuf, ln2_w, ln2_b, xn);

    {   // h1 = W_in * xn  (M=1020, K=192)
        dim3 grid(HW / 128, (2 * HIDDEN + 127) / 128, BATCH);
        mma_gemm_kernel<<<grid, 256>>>(w_in, xn, nullptr, h1, 2 * HIDDEN, DIM, DIM, HW);
    }
    {   // fused dwconv + geglu -> g
        dim3 grid(HGT / 8, HIDDEN, BATCH);
        dwconv_geglu_kernel<<<grid, 256>>>(h1, w_dw, g);
    }
    {   // out = W_out * g + y  (M=192, K=510 padded to 512)
        dim3 grid(HW / 128, (DIM + 127) / 128, BATCH);
        mma_gemm_kernel<<<grid, 256>>>(wp, g, ybuf, out, DIM, 512, HIDDEN, HW);
    }
}